// round 15
// baseline (speedup 1.0000x reference)
#include <cuda_runtime.h>
#include <cuda_bf16.h>
#include <math.h>
#include <stdint.h>

// Problem dimensions (fixed)
#define B_   128
#define T_   32
#define DIN  1024
#define H_   1024
#define V_   2048
#define A_   512
#define NROI 64

#define NB   296          // persistent grid: exactly 2 blocks per SM (148 SMs)
#define ASTR 40           // smem row stride (bf16) -> conflict-free ldmatrix
#define SK   4            // split-K factor for loop GEMM phases

// stage: A(hi/lo) 128 rows + W(hi/lo) 128 rows, ASTR stride, bf16
#define STAGE128 ((4 * 128) * ASTR * 2)   // 40960
#define PIPE 2
#define SMEM_GEMM (PIPE * STAGE128)       // 81920

typedef __nv_bfloat16 bf16;

// ---------------- fp32 scratch ----------------
__device__ float g_c[B_ * H_];
__device__ float g_va[(size_t)B_ * NROI * A_];
__device__ float g_pi[(size_t)B_ * T_ * 6 * H_];
__device__ float g_ps_p[SK][B_ * 5 * H_];
__device__ float g_pa_p[SK][B_ * 5 * H_];
__device__ float g_he_p[SK][B_ * A_];
__device__ float g_zero[128];

// ---------------- bf16 hi/lo split buffers ----------------
__device__ bf16 g_x_h[(size_t)B_ * T_ * DIN],   g_x_l[(size_t)B_ * T_ * DIN];
__device__ bf16 g_vis_h[(size_t)B_ * NROI * V_], g_vis_l[(size_t)B_ * NROI * V_];
__device__ bf16 g_mean_h[B_ * V_],  g_mean_l[B_ * V_];
__device__ bf16 g_h_h[B_ * H_],     g_h_l[B_ * H_];
__device__ bf16 g_ctx_h[B_ * V_],   g_ctx_l[B_ * V_];
__device__ bf16 g_Wi_h[(size_t)6 * H_ * DIN],  g_Wi_l[(size_t)6 * H_ * DIN];
__device__ bf16 g_Ws_h[(size_t)5 * H_ * H_],   g_Ws_l[(size_t)5 * H_ * H_];
__device__ bf16 g_Wa_h[(size_t)5 * H_ * V_],   g_Wa_l[(size_t)5 * H_ * V_];
__device__ bf16 g_Wv_h[(size_t)A_ * V_],       g_Wv_l[(size_t)A_ * V_];
__device__ bf16 g_Wh_h[(size_t)A_ * H_],       g_Wh_l[(size_t)A_ * H_];
__device__ bf16 g_W0h_h[(size_t)H_ * V_],      g_W0h_l[(size_t)H_ * V_];
__device__ bf16 g_W0c_h[(size_t)H_ * V_],      g_W0c_l[(size_t)H_ * V_];

// grid-wide barrier state
__device__ unsigned int g_bar_arrive;
__device__ volatile unsigned int g_bar_gen;

__device__ __forceinline__ float sigmoidf(float x) { return 1.0f / (1.0f + expf(-x)); }

__device__ __forceinline__ void grid_sync()
{
    __syncthreads();
    if (threadIdx.x == 0) {
        unsigned int gen = g_bar_gen;
        __threadfence();
        if (atomicAdd(&g_bar_arrive, 1u) == NB - 1) {
            g_bar_arrive = 0;
            __threadfence();
            g_bar_gen = gen + 1;
        } else {
            while (g_bar_gen == gen) { }
            __threadfence();
        }
    }
    __syncthreads();
}

// ---------------------------------------------------------------------------
// bf16 hi/lo split helpers
// ---------------------------------------------------------------------------
__device__ __forceinline__ void split_store4(bf16* __restrict__ ph,
                                             bf16* __restrict__ pl, float4 v)
{
    bf16 hx = __float2bfloat16(v.x), hy = __float2bfloat16(v.y);
    bf16 hz = __float2bfloat16(v.z), hw = __float2bfloat16(v.w);
    __nv_bfloat162 h0; h0.x = hx; h0.y = hy;
    __nv_bfloat162 h1; h1.x = hz; h1.y = hw;
    uint2 uh; uh.x = *(uint32_t*)&h0; uh.y = *(uint32_t*)&h1;
    *(uint2*)ph = uh;
    __nv_bfloat162 l0 = __floats2bfloat162_rn(v.x - __bfloat162float(hx),
                                              v.y - __bfloat162float(hy));
    __nv_bfloat162 l1 = __floats2bfloat162_rn(v.z - __bfloat162float(hz),
                                              v.w - __bfloat162float(hw));
    uint2 ul; ul.x = *(uint32_t*)&l0; ul.y = *(uint32_t*)&l1;
    *(uint2*)pl = ul;
}

__device__ __forceinline__ void store_split2(bf16* __restrict__ ph,
                                             bf16* __restrict__ pl,
                                             float a, float b)
{
    bf16 ha = __float2bfloat16(a), hb = __float2bfloat16(b);
    __nv_bfloat162 hp; hp.x = ha; hp.y = hb;
    *(uint32_t*)ph = *(uint32_t*)&hp;
    __nv_bfloat162 lp = __floats2bfloat162_rn(a - __bfloat162float(ha),
                                              b - __bfloat162float(hb));
    *(uint32_t*)pl = *(uint32_t*)&lp;
}

struct SJob  { const float* src; bf16* hi; bf16* lo; int n4; };
struct SJobs { SJob j[9]; };

__global__ void split_all_kernel(SJobs jobs)
{
    SJob jb = jobs.j[blockIdx.y];
    for (int i = blockIdx.x * 256 + threadIdx.x; i < jb.n4; i += gridDim.x * 256) {
        float4 v = ((const float4*)jb.src)[i];
        split_store4(jb.hi + 4 * i, jb.lo + 4 * i, v);
    }
}

__global__ void mean_vis_kernel(const float* __restrict__ visual,
                                const int* __restrict__ ls_rois)
{
    int b = blockIdx.x;
    int L = ls_rois[b];
    const float4* vb = (const float4*)(visual + (size_t)b * NROI * V_);
    float invL = 1.0f / (float)L;
    for (int v4 = threadIdx.x; v4 < V_ / 4; v4 += blockDim.x) {
        float4 s = make_float4(0.f, 0.f, 0.f, 0.f);
#pragma unroll 4
        for (int n = 0; n < NROI; n++) {
            if (n < L) {
                float4 x = vb[(size_t)n * (V_ / 4) + v4];
                s.x += x.x; s.y += x.y; s.z += x.z; s.w += x.w;
            }
        }
        s.x *= invL; s.y *= invL; s.z *= invL; s.w *= invL;
        split_store4(g_mean_h + b * V_ + v4 * 4, g_mean_l + b * V_ + v4 * 4, s);
    }
}

// ---------------------------------------------------------------------------
// MMA primitives
// ---------------------------------------------------------------------------
__device__ __forceinline__ uint32_t cvta_smem(const void* p)
{
    return (uint32_t)__cvta_generic_to_shared(p);
}

__device__ __forceinline__ void ldsm_x4(uint32_t addr, uint32_t* r)
{
    asm volatile("ldmatrix.sync.aligned.m8n8.x4.shared.b16 {%0,%1,%2,%3}, [%4];"
        : "=r"(r[0]), "=r"(r[1]), "=r"(r[2]), "=r"(r[3]) : "r"(addr));
}

__device__ __forceinline__ void mma16816(float c[4],
                                         const uint32_t a[4],
                                         uint32_t b0, uint32_t b1)
{
    asm volatile(
        "mma.sync.aligned.m16n8k16.row.col.f32.bf16.bf16.f32 "
        "{%0,%1,%2,%3}, {%4,%5,%6,%7}, {%8,%9}, {%0,%1,%2,%3};"
        : "+f"(c[0]), "+f"(c[1]), "+f"(c[2]), "+f"(c[3])
        : "r"(a[0]), "r"(a[1]), "r"(a[2]), "r"(a[3]), "r"(b0), "r"(b1));
}

__device__ __forceinline__ void cp16(uint32_t saddr, const void* g)
{
    asm volatile("cp.async.cg.shared.global [%0], [%1], 16;"
        :: "r"(saddr), "l"(g));
}

// ---------------------------------------------------------------------------
// 128x128 tile, 4(M)x2(N) warp grid; warp owns 32x64 output.
// C = (Ah+Al)@(Wh+Wl)^T + bias, 3-term split, fp32 accumulate.
// Per warp per k16: 12 LDSM.x4 feed 48 MMAs (0.25 LDSM/MMA; smem-traffic
// per MAC reduced ~1.5x vs 128x64 tile -> tensor-bound).
// PIPE=2 cp.async stages (40KB each) -> 2 blocks/SM co-resident.
// K % 32 == 0. SPLIT_OUT=1 writes bf16 hi/lo.
// ---------------------------------------------------------------------------
template<int SPLIT_OUT>
__device__ __forceinline__
void mma_tile128(uint32_t sbase,
                 const bf16* __restrict__ Ah, const bf16* __restrict__ Al, int lda,
                 const bf16* __restrict__ Wh, const bf16* __restrict__ Wl, int ldw,
                 const float* __restrict__ bias,
                 float* __restrict__ C, bf16* __restrict__ Ch, bf16* __restrict__ Cl,
                 int ldc, int K)
{
    const int tid  = threadIdx.x;
    const int lane = tid & 31, warp = tid >> 5;
    const int mq = warp & 3;          // M quadrant (32 rows)
    const int nh = warp >> 2;         // N half (64 cols)
    const uint32_t SB   = STAGE128;
    const uint32_t ALO  = 128 * ASTR * 2;        // A lo offset
    const uint32_t WOFF = 2 * 128 * ASTR * 2;    // W hi offset
    const uint32_t WLO  = 128 * ASTR * 2;        // W lo rel offset

    // cp.async: each thread does 2x cp16 for each of A-hi, A-lo, W-hi, W-lo
    const int rr = tid >> 1;              // row 0..127
    const int rc = (tid & 1) << 4;        // col 0 / 16

    const bf16* gAh = Ah + (size_t)rr * lda + rc;
    const bf16* gAl = Al + (size_t)rr * lda + rc;
    const bf16* gWh = Wh + (size_t)rr * ldw + rc;
    const bf16* gWl = Wl + (size_t)rr * ldw + rc;
    const uint32_t dAh = sbase + (rr * ASTR + rc) * 2;
    const uint32_t dAl = dAh + ALO;
    const uint32_t dWh = sbase + WOFF + (rr * ASTR + rc) * 2;
    const uint32_t dWl = dWh + WLO;

    // ldmatrix addresses
    uint32_t ah0, bh0;
    {
        int arow = mq * 32 + (lane & 15);
        int acol = (lane >> 4) << 3;
        ah0 = sbase + (arow * ASTR + acol) * 2;
        int brow = nh * 64 + ((lane >> 4) << 3) + (lane & 7);
        int bcol = ((lane >> 3) & 1) << 3;
        bh0 = sbase + WOFF + (brow * ASTR + bcol) * 2;
    }
    const uint32_t R16 = 16 * ASTR * 2;   // +16 rows (bytes)

    float acc[2][8][4];
#pragma unroll
    for (int f = 0; f < 2; f++)
#pragma unroll
        for (int j = 0; j < 8; j++)
#pragma unroll
            for (int e = 0; e < 4; e++) acc[f][j][e] = 0.0f;

    const int KC = K >> 5;

    // prologue: stage 0
    {
        cp16(dAh,      gAh);     cp16(dAh + 16, gAh + 8);
        cp16(dAl,      gAl);     cp16(dAl + 16, gAl + 8);
        cp16(dWh,      gWh);     cp16(dWh + 16, gWh + 8);
        cp16(dWl,      gWl);     cp16(dWl + 16, gWl + 8);
        asm volatile("cp.async.commit_group;");
    }

    for (int k = 0; k < KC; k++) {
        asm volatile("cp.async.wait_group 0;");
        __syncthreads();

        int kn = k + 1;
        if (kn < KC) {
            uint32_t off = (uint32_t)(kn & 1) * SB;
            int k0 = kn << 5;
            cp16(dAh + off,      gAh + k0);  cp16(dAh + off + 16, gAh + k0 + 8);
            cp16(dAl + off,      gAl + k0);  cp16(dAl + off + 16, gAl + k0 + 8);
            cp16(dWh + off,      gWh + k0);  cp16(dWh + off + 16, gWh + k0 + 8);
            cp16(dWl + off,      gWl + k0);  cp16(dWl + off + 16, gWl + k0 + 8);
        }
        asm volatile("cp.async.commit_group;");

        uint32_t off = (uint32_t)(k & 1) * SB;
#pragma unroll
        for (int s = 0; s < 2; s++) {
            uint32_t soff = off + s * 32;
            uint32_t a_h[2][4], a_l[2][4], b_h[4][4], b_l[4][4];
            ldsm_x4(ah0 + soff,       a_h[0]);
            ldsm_x4(ah0 + soff + R16, a_h[1]);
            ldsm_x4(ah0 + ALO + soff,       a_l[0]);
            ldsm_x4(ah0 + ALO + soff + R16, a_l[1]);
#pragma unroll
            for (int gq = 0; gq < 4; gq++)
                ldsm_x4(bh0 + soff + gq * R16, b_h[gq]);
            // term 1: hi*hi
#pragma unroll
            for (int f = 0; f < 2; f++)
#pragma unroll
                for (int j = 0; j < 8; j++)
                    mma16816(acc[f][j], a_h[f], b_h[j >> 1][(j & 1) << 1],
                             b_h[j >> 1][((j & 1) << 1) + 1]);
#pragma unroll
            for (int gq = 0; gq < 4; gq++)
                ldsm_x4(bh0 + WLO + soff + gq * R16, b_l[gq]);
            // term 2: hi*lo
#pragma unroll
            for (int f = 0; f < 2; f++)
#pragma unroll
                for (int j = 0; j < 8; j++)
                    mma16816(acc[f][j], a_h[f], b_l[j >> 1][(j & 1) << 1],
                             b_l[j >> 1][((j & 1) << 1) + 1]);
            // term 3: lo*hi
#pragma unroll
            for (int f = 0; f < 2; f++)
#pragma unroll
                for (int j = 0; j < 8; j++)
                    mma16816(acc[f][j], a_l[f], b_h[j >> 1][(j & 1) << 1],
                             b_h[j >> 1][((j & 1) << 1) + 1]);
        }
    }
    __syncthreads();

    const int g = lane >> 2, t = lane & 3;
#pragma unroll
    for (int f = 0; f < 2; f++) {
        int r0 = mq * 32 + f * 16 + g;
        int r1 = r0 + 8;
#pragma unroll
        for (int j = 0; j < 8; j++) {
            int col = nh * 64 + 8 * j + 2 * t;
            float2 bv = *(const float2*)(bias + col);
            float v00 = acc[f][j][0] + bv.x, v01 = acc[f][j][1] + bv.y;
            float v10 = acc[f][j][2] + bv.x, v11 = acc[f][j][3] + bv.y;
            if (SPLIT_OUT) {
                store_split2(Ch + (size_t)r0 * ldc + col, Cl + (size_t)r0 * ldc + col, v00, v01);
                store_split2(Ch + (size_t)r1 * ldc + col, Cl + (size_t)r1 * ldc + col, v10, v11);
            } else {
                *(float2*)(C + (size_t)r0 * ldc + col) = make_float2(v00, v01);
                *(float2*)(C + (size_t)r1 * ldc + col) = make_float2(v10, v11);
            }
        }
    }
}

// Precompute GEMM: grid (N/128, M/128).
__global__ __launch_bounds__(256, 2)
void mma_gemm_nt(const bf16* __restrict__ Ah, const bf16* __restrict__ Al,
                 const bf16* __restrict__ Wh, const bf16* __restrict__ Wl,
                 const float* __restrict__ bias, float* __restrict__ C,
                 int N, int K)
{
    extern __shared__ char dynsm[];
    uint32_t sbase = cvta_smem(dynsm);
    int m0 = blockIdx.y * 128;
    int n0 = blockIdx.x * 128;
    mma_tile128<0>(sbase,
                   Ah + (size_t)m0 * K, Al + (size_t)m0 * K, K,
                   Wh + (size_t)n0 * K, Wl + (size_t)n0 * K, K,
                   bias + n0, C + (size_t)m0 * N + n0, nullptr, nullptr,
                   N, K);
}

// h0 (z=0, split-bf16 output) and c0 (z=1, fp32) in one launch.
__global__ __launch_bounds__(256, 2)
void h0c0_kernel(const float* __restrict__ b0h, const float* __restrict__ b0c)
{
    extern __shared__ char dynsm[];
    uint32_t sbase = cvta_smem(dynsm);
    int n0 = blockIdx.x * 128;
    if (blockIdx.z == 0) {
        mma_tile128<1>(sbase, g_mean_h, g_mean_l, V_,
                       g_W0h_h + (size_t)n0 * V_, g_W0h_l + (size_t)n0 * V_, V_,
                       b0h + n0, nullptr, g_h_h + n0, g_h_l + n0, H_, V_);
    } else {
        mma_tile128<0>(sbase, g_mean_h, g_mean_l, V_,
                       g_W0c_h + (size_t)n0 * V_, g_W0c_l + (size_t)n0 * V_, V_,
                       b0c + n0, g_c + n0, nullptr, nullptr, H_, V_);
    }
}

// ---------------------------------------------------------------------------
// Attention: block pair (b, b+128), each writes half the ctx V-range.
// ---------------------------------------------------------------------------
__device__ __forceinline__
void attn_work(int b, int vhalf, const float* __restrict__ visual,
               const float* __restrict__ Wp, const float* __restrict__ bp,
               const int* __restrict__ ls_rois,
               float* he_s, float* wp_s, float* att)
{
    int tid = threadIdx.x;
    int warp = tid >> 5, lane = tid & 31;

    if (tid < 128) {
        float4 hs = make_float4(0.f, 0.f, 0.f, 0.f);
#pragma unroll
        for (int kp = 0; kp < SK; kp++) {
            float4 hv = ((const float4*)(g_he_p[kp] + b * A_))[tid];
            hs.x += hv.x; hs.y += hv.y; hs.z += hv.z; hs.w += hv.w;
        }
        ((float4*)he_s)[tid] = hs;
        ((float4*)wp_s)[tid] = ((const float4*)Wp)[tid];
    }
    __syncthreads();

    int L = ls_rois[b];

    for (int n = warp; n < NROI; n += 8) {
        float s = 0.0f;
        if (n < L) {
            const float4* vrow = (const float4*)(g_va + ((size_t)b * NROI + n) * A_);
            const float4* he4 = (const float4*)he_s;
            const float4* wp4 = (const float4*)wp_s;
#pragma unroll
            for (int a4 = lane; a4 < A_ / 4; a4 += 32) {
                float4 v = vrow[a4];
                float4 h = he4[a4];
                float4 p = wp4[a4];
                s += p.x * fmaxf(v.x + h.x, 0.0f);
                s += p.y * fmaxf(v.y + h.y, 0.0f);
                s += p.z * fmaxf(v.z + h.z, 0.0f);
                s += p.w * fmaxf(v.w + h.w, 0.0f);
            }
        }
#pragma unroll
        for (int o = 16; o; o >>= 1) s += __shfl_xor_sync(0xffffffffu, s, o);
        if (lane == 0) att[n] = s + bp[0];
    }
    __syncthreads();

    if (tid == 0) {
        float mx = -3.0e38f;
        for (int n = 0; n < L; n++) mx = fmaxf(mx, att[n]);
        float den = 0.0f;
        for (int n = 0; n < L; n++) { float e = expf(att[n] - mx); att[n] = e; den += e; }
        float inv = 1.0f / den;
        for (int n = 0; n < L; n++) att[n] *= inv;
        for (int n = L; n < NROI; n++) att[n] = 0.0f;
    }
    __syncthreads();

    const float4* vb4 = (const float4*)(visual + (size_t)b * NROI * V_);
    int v4 = vhalf * (V_ / 8) + tid;
    float4 s = make_float4(0.f, 0.f, 0.f, 0.f);
#pragma unroll 8
    for (int n = 0; n < NROI; n++) {
        float a = att[n];
        float4 x = vb4[(size_t)n * (V_ / 4) + v4];
        s.x += a * x.x; s.y += a * x.y; s.z += a * x.z; s.w += a * x.w;
    }
    split_store4(g_ctx_h + b * V_ + v4 * 4, g_ctx_l + b * V_ + v4 * 4, s);
    __syncthreads();
}

// ---------------------------------------------------------------------------
// LSTM gates + highway + state update + y. Sums SK ps + SK pa partials.
// ---------------------------------------------------------------------------
__device__ __forceinline__
void gate_work(int b, int t, const float* __restrict__ Wo,
               const float* __restrict__ bo, const int* __restrict__ seq_lens,
               float* __restrict__ y, float* red)
{
    const int HQ = H_ / 4;
    int tid = threadIdx.x;
    bool valid = (t < seq_lens[b]);

    const float4* pi = (const float4*)(g_pi + ((size_t)b * T_ + t) * (6 * H_));
    float4* c4 = (float4*)(g_c + b * H_);

    float g[5][4];
#pragma unroll
    for (int kg = 0; kg < 5; kg++) {
        float4 a = pi[kg * HQ + tid];
        float gx = a.x, gy = a.y, gz = a.z, gw = a.w;
#pragma unroll
        for (int kp = 0; kp < SK; kp++) {
            float4 q = ((const float4*)(g_ps_p[kp] + (size_t)b * (5 * H_)))[kg * HQ + tid];
            float4 r = ((const float4*)(g_pa_p[kp] + (size_t)b * (5 * H_)))[kg * HQ + tid];
            gx += q.x + r.x; gy += q.y + r.y; gz += q.z + r.z; gw += q.w + r.w;
        }
        g[kg][0] = gx; g[kg][1] = gy; g[kg][2] = gz; g[kg][3] = gw;
    }
    float4 s5 = pi[5 * HQ + tid];
    float pi5[4] = {s5.x, s5.y, s5.z, s5.w};
    float4 cv = c4[tid];
    float cc[4] = {cv.x, cv.y, cv.z, cv.w};
    float4 wo = ((const float4*)Wo)[tid];
    float wof[4] = {wo.x, wo.y, wo.z, wo.w};

    float out[4], mem[4], part = 0.0f;
#pragma unroll
    for (int e = 0; e < 4; e++) {
        float ig = sigmoidf(g[0][e]);
        float fg = sigmoidf(g[1][e]);
        float mi = tanhf(g[2][e]);
        float og = sigmoidf(g[3][e]);
        float m  = ig * mi + fg * cc[e];
        float o  = og * tanhf(m);
        float hw = sigmoidf(g[4][e]);
        out[e] = hw * o + (1.0f - hw) * pi5[e];
        mem[e] = m;
        part += out[e] * wof[e];
    }

    if (valid) {
        split_store4(g_h_h + b * H_ + 4 * tid, g_h_l + b * H_ + 4 * tid,
                     make_float4(out[0], out[1], out[2], out[3]));
        c4[tid] = make_float4(mem[0], mem[1], mem[2], mem[3]);
    }

#pragma unroll
    for (int o = 16; o; o >>= 1) part += __shfl_xor_sync(0xffffffffu, part, o);
    if ((tid & 31) == 0) red[tid >> 5] = part;
    __syncthreads();
    if (tid == 0) {
        float s = 0.0f;
#pragma unroll
        for (int w = 0; w < 8; w++) s += red[w];
        y[b * T_ + t] = valid ? (s + bo[0]) : 0.0f;
    }
    __syncthreads();
}

// ---------------------------------------------------------------------------
// Persistent recurrent-loop kernel: 128x128 tensor tiles, split-K x4.
// ---------------------------------------------------------------------------
__global__ __launch_bounds__(256, 2)
void loop_kernel(const float* __restrict__ bs, const float* __restrict__ bh,
                 const float* __restrict__ ba,
                 const float* __restrict__ Wp, const float* __restrict__ bp,
                 const float* __restrict__ Wo, const float* __restrict__ bo,
                 const float* __restrict__ visual,
                 const int* __restrict__ ls_rois,
                 const int* __restrict__ seq_lens,
                 float* __restrict__ y)
{
    extern __shared__ char dynsm[];
    uint32_t sbase = cvta_smem(dynsm);

    __shared__ float he_s[A_];
    __shared__ float wp_s[A_];
    __shared__ float att[NROI];
    __shared__ float red[8];

    const int NT1 = ((5 * H_ + A_) / 128) * SK;   // 176 tiles, K=256
    const int NT2 = ((5 * H_) / 128) * SK;        // 160 tiles, K=512
    const int KH1 = H_ / SK;                       // 256
    const int KH2 = V_ / SK;                       // 512

    for (int t = 0; t < T_; t++) {
        // ---- phase 1: [ps | he] = h @ [Ws ; Wh]^T ----
        for (int tile = blockIdx.x; tile < NT1; tile += NB) {
            int kp = tile & (SK - 1), nt = tile >> 2;
            int n0 = nt << 7;
            const bf16* Ahp = g_h_h + kp * KH1;
            const bf16* Alp = g_h_l + kp * KH1;
            if (n0 < 5 * H_) {
                mma_tile128<0>(sbase, Ahp, Alp, H_,
                         g_Ws_h + (size_t)n0 * H_ + kp * KH1,
                         g_Ws_l + (size_t)n0 * H_ + kp * KH1, H_,
                         kp ? g_zero : (bs + n0),
                         g_ps_p[kp] + n0, nullptr, nullptr, 5 * H_, KH1);
            } else {
                int m = n0 - 5 * H_;
                mma_tile128<0>(sbase, Ahp, Alp, H_,
                         g_Wh_h + (size_t)m * H_ + kp * KH1,
                         g_Wh_l + (size_t)m * H_ + kp * KH1, H_,
                         kp ? g_zero : (bh + m),
                         g_he_p[kp] + m, nullptr, nullptr, A_, KH1);
            }
        }
        grid_sync();

        // ---- phase 2: attention -> ctx (2 blocks per batch element) ----
        if (blockIdx.x < 2 * B_)
            attn_work(blockIdx.x & (B_ - 1), blockIdx.x >> 7,
                      visual, Wp, bp, ls_rois, he_s, wp_s, att);
        grid_sync();

        // ---- phase 3: pa = ctx @ Wa^T ----
        for (int tile = blockIdx.x; tile < NT2; tile += NB) {
            int kp = tile & (SK - 1), nt = tile >> 2;
            int n0 = nt << 7;
            mma_tile128<0>(sbase,
                     g_ctx_h + kp * KH2, g_ctx_l + kp * KH2, V_,
                     g_Wa_h + (size_t)n0 * V_ + kp * KH2,
                     g_Wa_l + (size_t)n0 * V_ + kp * KH2, V_,
                     kp ? g_zero : (ba + n0),
                     g_pa_p[kp] + n0, nullptr, nullptr, 5 * H_, KH2);
        }
        grid_sync();

        // ---- phase 4: gates + state update + y ----
        if (blockIdx.x < B_)
            gate_work(blockIdx.x, t, Wo, bo, seq_lens, y, red);
        grid_sync();
    }
}

// ---------------------------------------------------------------------------
extern "C" void kernel_launch(void* const* d_in, const int* in_sizes, int n_in,
                              void* d_out, int out_size)
{
    const float* x      = (const float*)d_in[0];
    const float* visual = (const float*)d_in[1];
    const float* Wi     = (const float*)d_in[2];
    const float* bi     = (const float*)d_in[3];
    const float* Ws     = (const float*)d_in[4];
    const float* bs     = (const float*)d_in[5];
    const float* Wa     = (const float*)d_in[6];
    const float* ba     = (const float*)d_in[7];
    const float* Wv     = (const float*)d_in[8];
    const float* bv     = (const float*)d_in[9];
    const float* Wh     = (const float*)d_in[10];
    const float* bh     = (const float*)d_in[11];
    const float* Wp     = (const float*)d_in[12];
    const float* bp     = (const float*)d_in[13];
    const float* W0h    = (const float*)d_in[14];
    const float* b0h    = (const float*)d_in[15];
    const float* W0c    = (const float*)d_in[16];
    const float* b0c    = (const float*)d_in[17];
    const float* Wo     = (const float*)d_in[18];
    const float* bo     = (const float*)d_in[19];
    const int* ls_rois  = (const int*)d_in[20];
    const int* seq_lens = (const int*)d_in[21];
    float* y = (float*)d_out;

    cudaFuncSetAttribute(loop_kernel,
                         cudaFuncAttributeMaxDynamicSharedMemorySize, SMEM_GEMM);
    cudaFuncSetAttribute(mma_gemm_nt,
                         cudaFuncAttributeMaxDynamicSharedMemorySize, SMEM_GEMM);
    cudaFuncSetAttribute(h0c0_kernel,
                         cudaFuncAttributeMaxDynamicSharedMemorySize, SMEM_GEMM);

    float *p_va, *p_pi;
    cudaGetSymbolAddress((void**)&p_va, g_va);
    cudaGetSymbolAddress((void**)&p_pi, g_pi);
    bf16 *px_h, *px_l, *pv_h, *pv_l;
    bf16 *pWi_h, *pWi_l, *pWs_h, *pWs_l, *pWa_h, *pWa_l, *pWv_h, *pWv_l;
    bf16 *pWh_h, *pWh_l, *pW0h_h, *pW0h_l, *pW0c_h, *pW0c_l;
    cudaGetSymbolAddress((void**)&px_h, g_x_h);   cudaGetSymbolAddress((void**)&px_l, g_x_l);
    cudaGetSymbolAddress((void**)&pv_h, g_vis_h); cudaGetSymbolAddress((void**)&pv_l, g_vis_l);
    cudaGetSymbolAddress((void**)&pWi_h, g_Wi_h); cudaGetSymbolAddress((void**)&pWi_l, g_Wi_l);
    cudaGetSymbolAddress((void**)&pWs_h, g_Ws_h); cudaGetSymbolAddress((void**)&pWs_l, g_Ws_l);
    cudaGetSymbolAddress((void**)&pWa_h, g_Wa_h); cudaGetSymbolAddress((void**)&pWa_l, g_Wa_l);
    cudaGetSymbolAddress((void**)&pWv_h, g_Wv_h); cudaGetSymbolAddress((void**)&pWv_l, g_Wv_l);
    cudaGetSymbolAddress((void**)&pWh_h, g_Wh_h); cudaGetSymbolAddress((void**)&pWh_l, g_Wh_l);
    cudaGetSymbolAddress((void**)&pW0h_h, g_W0h_h); cudaGetSymbolAddress((void**)&pW0h_l, g_W0h_l);
    cudaGetSymbolAddress((void**)&pW0c_h, g_W0c_h); cudaGetSymbolAddress((void**)&pW0c_l, g_W0c_l);

    // ---- launch 1: all loop-invariant splits fused ----
    SJobs jobs;
    jobs.j[0] = { x,      px_h,  px_l,  (B_ * T_ * DIN) / 4 };
    jobs.j[1] = { visual, pv_h,  pv_l,  (B_ * NROI * V_) / 4 };
    jobs.j[2] = { Wi,     pWi_h, pWi_l, (6 * H_ * DIN) / 4 };
    jobs.j[3] = { Ws,     pWs_h, pWs_l, (5 * H_ * H_) / 4 };
    jobs.j[4] = { Wa,     pWa_h, pWa_l, (5 * H_ * V_) / 4 };
    jobs.j[5] = { Wv,     pWv_h, pWv_l, (A_ * V_) / 4 };
    jobs.j[6] = { Wh,     pWh_h, pWh_l, (A_ * H_) / 4 };
    jobs.j[7] = { W0h,    pW0h_h, pW0h_l, (H_ * V_) / 4 };
    jobs.j[8] = { W0c,    pW0c_h, pW0c_l, (H_ * V_) / 4 };
    split_all_kernel<<<dim3(148, 9), 256>>>(jobs);

    // ---- launch 2: mean (writes splits directly) ----
    mean_vis_kernel<<<B_, 256>>>(visual, ls_rois);

    // ---- launch 3: pi = x @ Wi^T + bi ----
    mma_gemm_nt<<<dim3(6 * H_ / 128, B_ * T_ / 128), 256, SMEM_GEMM>>>(
        px_h, px_l, pWi_h, pWi_l, bi, p_pi, 6 * H_, DIN);

    // ---- launch 4: va = visual @ Wv^T + bv ----
    mma_gemm_nt<<<dim3(A_ / 128, B_ * NROI / 128), 256, SMEM_GEMM>>>(
        pv_h, pv_l, pWv_h, pWv_l, bv, p_va, A_, V_);

    // ---- launch 5: h0 (split output) + c0 (fp32) ----
    h0c0_kernel<<<dim3(H_ / 128, 1, 2), 256, SMEM_GEMM>>>(b0h, b0c);

    // ---- launch 6: entire recurrent loop ----
    loop_kernel<<<NB, 256, SMEM_GEMM>>>(bs, bh, ba, Wp, bp, Wo, bo,
                                        visual, ls_rois, seq_lens, y);
}

// round 16
// speedup vs baseline: 1.0736x; 1.0736x over previous
#include <cuda_runtime.h>
#include <cuda_bf16.h>
#include <math.h>
#include <stdint.h>

// Problem dimensions (fixed)
#define B_   128
#define T_   32
#define DIN  1024
#define H_   1024
#define V_   2048
#define A_   512
#define NROI 64

#define NB   296          // persistent grid: exactly 2 blocks per SM (148 SMs)
#define ASTR 40           // smem row stride (bf16) -> conflict-free ldmatrix
#define SK   4            // split-K factor for loop GEMM phases

// loop stage: A(hi/lo) 128 rows + W(hi/lo) 64 rows
#define STAGE64 ((2 * 128 + 2 * 64) * ASTR * 2)    // 30720
#define PIPE_LOOP 3
#define SMEM_LOOP (PIPE_LOOP * STAGE64)            // 92160
// precompute stage: A(hi/lo) 128 rows + W(hi/lo) 128 rows
#define STAGE128 ((4 * 128) * ASTR * 2)            // 40960
#define PIPE_PRE 2
#define SMEM_PRE (PIPE_PRE * STAGE128)             // 81920

typedef __nv_bfloat16 bf16;

// ---------------- fp32 scratch ----------------
__device__ float g_c[B_ * H_];
__device__ float g_va[(size_t)B_ * NROI * A_];
__device__ float g_pi[(size_t)B_ * T_ * 6 * H_];
__device__ float g_ps_p[SK][B_ * 5 * H_];
__device__ float g_pa_p[SK][B_ * 5 * H_];
__device__ float g_he_p[SK][B_ * A_];
__device__ float g_zero[128];

// ---------------- bf16 hi/lo split buffers ----------------
__device__ bf16 g_x_h[(size_t)B_ * T_ * DIN],   g_x_l[(size_t)B_ * T_ * DIN];
__device__ bf16 g_vis_h[(size_t)B_ * NROI * V_], g_vis_l[(size_t)B_ * NROI * V_];
__device__ bf16 g_mean_h[B_ * V_],  g_mean_l[B_ * V_];
__device__ bf16 g_h_h[B_ * H_],     g_h_l[B_ * H_];
__device__ bf16 g_ctx_h[B_ * V_],   g_ctx_l[B_ * V_];
__device__ bf16 g_Wi_h[(size_t)6 * H_ * DIN],  g_Wi_l[(size_t)6 * H_ * DIN];
__device__ bf16 g_Ws_h[(size_t)5 * H_ * H_],   g_Ws_l[(size_t)5 * H_ * H_];
__device__ bf16 g_Wa_h[(size_t)5 * H_ * V_],   g_Wa_l[(size_t)5 * H_ * V_];
__device__ bf16 g_Wv_h[(size_t)A_ * V_],       g_Wv_l[(size_t)A_ * V_];
__device__ bf16 g_Wh_h[(size_t)A_ * H_],       g_Wh_l[(size_t)A_ * H_];
__device__ bf16 g_W0h_h[(size_t)H_ * V_],      g_W0h_l[(size_t)H_ * V_];
__device__ bf16 g_W0c_h[(size_t)H_ * V_],      g_W0c_l[(size_t)H_ * V_];

// grid-wide barrier state
__device__ unsigned int g_bar_arrive;
__device__ volatile unsigned int g_bar_gen;

__device__ __forceinline__ float sigmoidf(float x) { return 1.0f / (1.0f + expf(-x)); }

__device__ __forceinline__ void grid_sync()
{
    __syncthreads();
    if (threadIdx.x == 0) {
        unsigned int gen = g_bar_gen;
        __threadfence();
        if (atomicAdd(&g_bar_arrive, 1u) == NB - 1) {
            g_bar_arrive = 0;
            __threadfence();
            g_bar_gen = gen + 1;
        } else {
            while (g_bar_gen == gen) { }
            __threadfence();
        }
    }
    __syncthreads();
}

// ---------------------------------------------------------------------------
// bf16 hi/lo split helpers
// ---------------------------------------------------------------------------
__device__ __forceinline__ void split_store4(bf16* __restrict__ ph,
                                             bf16* __restrict__ pl, float4 v)
{
    bf16 hx = __float2bfloat16(v.x), hy = __float2bfloat16(v.y);
    bf16 hz = __float2bfloat16(v.z), hw = __float2bfloat16(v.w);
    __nv_bfloat162 h0; h0.x = hx; h0.y = hy;
    __nv_bfloat162 h1; h1.x = hz; h1.y = hw;
    uint2 uh; uh.x = *(uint32_t*)&h0; uh.y = *(uint32_t*)&h1;
    *(uint2*)ph = uh;
    __nv_bfloat162 l0 = __floats2bfloat162_rn(v.x - __bfloat162float(hx),
                                              v.y - __bfloat162float(hy));
    __nv_bfloat162 l1 = __floats2bfloat162_rn(v.z - __bfloat162float(hz),
                                              v.w - __bfloat162float(hw));
    uint2 ul; ul.x = *(uint32_t*)&l0; ul.y = *(uint32_t*)&l1;
    *(uint2*)pl = ul;
}

__device__ __forceinline__ void store_split2(bf16* __restrict__ ph,
                                             bf16* __restrict__ pl,
                                             float a, float b)
{
    bf16 ha = __float2bfloat16(a), hb = __float2bfloat16(b);
    __nv_bfloat162 hp; hp.x = ha; hp.y = hb;
    *(uint32_t*)ph = *(uint32_t*)&hp;
    __nv_bfloat162 lp = __floats2bfloat162_rn(a - __bfloat162float(ha),
                                              b - __bfloat162float(hb));
    *(uint32_t*)pl = *(uint32_t*)&lp;
}

struct SJob  { const float* src; bf16* hi; bf16* lo; int n4; };
struct SJobs { SJob j[9]; };

__global__ void split_all_kernel(SJobs jobs)
{
    SJob jb = jobs.j[blockIdx.y];
    for (int i = blockIdx.x * 256 + threadIdx.x; i < jb.n4; i += gridDim.x * 256) {
        float4 v = ((const float4*)jb.src)[i];
        split_store4(jb.hi + 4 * i, jb.lo + 4 * i, v);
    }
}

__global__ void mean_vis_kernel(const float* __restrict__ visual,
                                const int* __restrict__ ls_rois)
{
    int b = blockIdx.x;
    int L = ls_rois[b];
    const float4* vb = (const float4*)(visual + (size_t)b * NROI * V_);
    float invL = 1.0f / (float)L;
    for (int v4 = threadIdx.x; v4 < V_ / 4; v4 += blockDim.x) {
        float4 s = make_float4(0.f, 0.f, 0.f, 0.f);
#pragma unroll 4
        for (int n = 0; n < NROI; n++) {
            if (n < L) {
                float4 x = vb[(size_t)n * (V_ / 4) + v4];
                s.x += x.x; s.y += x.y; s.z += x.z; s.w += x.w;
            }
        }
        s.x *= invL; s.y *= invL; s.z *= invL; s.w *= invL;
        split_store4(g_mean_h + b * V_ + v4 * 4, g_mean_l + b * V_ + v4 * 4, s);
    }
}

// ---------------------------------------------------------------------------
// MMA primitives
// ---------------------------------------------------------------------------
__device__ __forceinline__ uint32_t cvta_smem(const void* p)
{
    return (uint32_t)__cvta_generic_to_shared(p);
}

__device__ __forceinline__ void ldsm_x4(uint32_t addr, uint32_t* r)
{
    asm volatile("ldmatrix.sync.aligned.m8n8.x4.shared.b16 {%0,%1,%2,%3}, [%4];"
        : "=r"(r[0]), "=r"(r[1]), "=r"(r[2]), "=r"(r[3]) : "r"(addr));
}

__device__ __forceinline__ void mma16816(float c[4],
                                         const uint32_t a[4],
                                         uint32_t b0, uint32_t b1)
{
    asm volatile(
        "mma.sync.aligned.m16n8k16.row.col.f32.bf16.bf16.f32 "
        "{%0,%1,%2,%3}, {%4,%5,%6,%7}, {%8,%9}, {%0,%1,%2,%3};"
        : "+f"(c[0]), "+f"(c[1]), "+f"(c[2]), "+f"(c[3])
        : "r"(a[0]), "r"(a[1]), "r"(a[2]), "r"(a[3]), "r"(b0), "r"(b1));
}

__device__ __forceinline__ void cp16(uint32_t saddr, const void* g)
{
    asm volatile("cp.async.cg.shared.global [%0], [%1], 16;"
        :: "r"(saddr), "l"(g));
}

// ---------------------------------------------------------------------------
// LOOP TILE: 128x64, 4(M)x2(N) warps (warp owns 32x32). PIPE_LOOP stages.
// Best-measured loop configuration (R13).
// ---------------------------------------------------------------------------
__device__ __forceinline__
void mma_tile64(uint32_t sbase,
                const bf16* __restrict__ Ah, const bf16* __restrict__ Al, int lda,
                const bf16* __restrict__ Wh, const bf16* __restrict__ Wl, int ldw,
                const float* __restrict__ bias, float* __restrict__ C,
                int ldc, int K)
{
    const int tid  = threadIdx.x;
    const int lane = tid & 31, warp = tid >> 5;
    const int mq = warp & 3;
    const int nh = warp >> 2;
    const uint32_t SB   = STAGE64;
    const uint32_t ALO  = 128 * ASTR * 2;
    const uint32_t WOFF = 2 * 128 * ASTR * 2;
    const uint32_t WLO  = 64 * ASTR * 2;

    const int ar = tid >> 1;
    const int ac = (tid & 1) << 4;
    const int wr = tid >> 2;
    const int wc = (tid & 3) << 3;

    const bf16* gAh = Ah + (size_t)ar * lda + ac;
    const bf16* gAl = Al + (size_t)ar * lda + ac;
    const bf16* gWh = Wh + (size_t)wr * ldw + wc;
    const bf16* gWl = Wl + (size_t)wr * ldw + wc;
    const uint32_t dAh = sbase + (ar * ASTR + ac) * 2;
    const uint32_t dAl = dAh + ALO;
    const uint32_t dWh = sbase + WOFF + (wr * ASTR + wc) * 2;
    const uint32_t dWl = dWh + WLO;

    uint32_t ah_ad[2], bh_ad[2];
    {
        int arow = lane & 15;
        int acol = (lane >> 4) << 3;
        ah_ad[0] = sbase + ((mq * 32 + arow) * ASTR + acol) * 2;
        ah_ad[1] = ah_ad[0] + 16 * ASTR * 2;
        int brow = ((lane >> 4) << 3) + (lane & 7);
        int bcol = ((lane >> 3) & 1) << 3;
        bh_ad[0] = sbase + WOFF + ((nh * 32 + brow) * ASTR + bcol) * 2;
        bh_ad[1] = bh_ad[0] + 16 * ASTR * 2;
    }

    float acc[2][4][4];
#pragma unroll
    for (int f = 0; f < 2; f++)
#pragma unroll
        for (int j = 0; j < 4; j++)
#pragma unroll
            for (int e = 0; e < 4; e++) acc[f][j][e] = 0.0f;

    const int KC = K >> 5;

#pragma unroll
    for (int s = 0; s < PIPE_LOOP - 1; s++) {
        int k0 = s << 5;
        uint32_t off = s * SB;
        cp16(dAh + off,      gAh + k0);
        cp16(dAh + off + 16, gAh + k0 + 8);
        cp16(dAl + off,      gAl + k0);
        cp16(dAl + off + 16, gAl + k0 + 8);
        cp16(dWh + off,      gWh + k0);
        cp16(dWl + off,      gWl + k0);
        asm volatile("cp.async.commit_group;");
    }

    for (int k = 0; k < KC; k++) {
        asm volatile("cp.async.wait_group %0;" :: "n"(PIPE_LOOP - 2));
        __syncthreads();

        int kn = k + PIPE_LOOP - 1;
        if (kn < KC) {
            uint32_t off = (uint32_t)(kn % PIPE_LOOP) * SB;
            int k0 = kn << 5;
            cp16(dAh + off,      gAh + k0);
            cp16(dAh + off + 16, gAh + k0 + 8);
            cp16(dAl + off,      gAl + k0);
            cp16(dAl + off + 16, gAl + k0 + 8);
            cp16(dWh + off,      gWh + k0);
            cp16(dWl + off,      gWl + k0);
        }
        asm volatile("cp.async.commit_group;");

        uint32_t off = (uint32_t)(k % PIPE_LOOP) * SB;
#pragma unroll
        for (int s = 0; s < 2; s++) {
            uint32_t a_h[2][4], a_l[2][4], b_h[2][4], b_l[2][4];
            ldsm_x4(ah_ad[0] + off + s * 32,       a_h[0]);
            ldsm_x4(ah_ad[1] + off + s * 32,       a_h[1]);
            ldsm_x4(ah_ad[0] + ALO + off + s * 32, a_l[0]);
            ldsm_x4(ah_ad[1] + ALO + off + s * 32, a_l[1]);
            ldsm_x4(bh_ad[0] + off + s * 32,       b_h[0]);
            ldsm_x4(bh_ad[1] + off + s * 32,       b_h[1]);
            ldsm_x4(bh_ad[0] + WLO + off + s * 32, b_l[0]);
            ldsm_x4(bh_ad[1] + WLO + off + s * 32, b_l[1]);
#pragma unroll
            for (int f = 0; f < 2; f++)
#pragma unroll
                for (int j = 0; j < 4; j++) {
                    int jf = j >> 1, jr = (j & 1) << 1;
                    mma16816(acc[f][j], a_h[f], b_h[jf][jr], b_h[jf][jr + 1]);
                }
#pragma unroll
            for (int f = 0; f < 2; f++)
#pragma unroll
                for (int j = 0; j < 4; j++) {
                    int jf = j >> 1, jr = (j & 1) << 1;
                    mma16816(acc[f][j], a_h[f], b_l[jf][jr], b_l[jf][jr + 1]);
                }
#pragma unroll
            for (int f = 0; f < 2; f++)
#pragma unroll
                for (int j = 0; j < 4; j++) {
                    int jf = j >> 1, jr = (j & 1) << 1;
                    mma16816(acc[f][j], a_l[f], b_h[jf][jr], b_h[jf][jr + 1]);
                }
        }
    }
    __syncthreads();

    const int g = lane >> 2, t = lane & 3;
#pragma unroll
    for (int f = 0; f < 2; f++) {
        int r0 = mq * 32 + f * 16 + g;
        int r1 = r0 + 8;
#pragma unroll
        for (int j = 0; j < 4; j++) {
            int col = nh * 32 + 8 * j + 2 * t;
            float2 bv = *(const float2*)(bias + col);
            *(float2*)(C + (size_t)r0 * ldc + col) =
                make_float2(acc[f][j][0] + bv.x, acc[f][j][1] + bv.y);
            *(float2*)(C + (size_t)r1 * ldc + col) =
                make_float2(acc[f][j][2] + bv.x, acc[f][j][3] + bv.y);
        }
    }
}

// ---------------------------------------------------------------------------
// PRECOMPUTE TILE: 128x128, 4(M)x2(N) warps (warp owns 32x64). PIPE_PRE=2.
// Measured 1.18x faster per-tile than 64-wide (tensor 50.3%).
// ---------------------------------------------------------------------------
template<int SPLIT_OUT>
__device__ __forceinline__
void mma_tile128(uint32_t sbase,
                 const bf16* __restrict__ Ah, const bf16* __restrict__ Al, int lda,
                 const bf16* __restrict__ Wh, const bf16* __restrict__ Wl, int ldw,
                 const float* __restrict__ bias,
                 float* __restrict__ C, bf16* __restrict__ Ch, bf16* __restrict__ Cl,
                 int ldc, int K)
{
    const int tid  = threadIdx.x;
    const int lane = tid & 31, warp = tid >> 5;
    const int mq = warp & 3;
    const int nh = warp >> 2;
    const uint32_t SB   = STAGE128;
    const uint32_t ALO  = 128 * ASTR * 2;
    const uint32_t WOFF = 2 * 128 * ASTR * 2;
    const uint32_t WLO  = 128 * ASTR * 2;

    const int rr = tid >> 1;
    const int rc = (tid & 1) << 4;

    const bf16* gAh = Ah + (size_t)rr * lda + rc;
    const bf16* gAl = Al + (size_t)rr * lda + rc;
    const bf16* gWh = Wh + (size_t)rr * ldw + rc;
    const bf16* gWl = Wl + (size_t)rr * ldw + rc;
    const uint32_t dAh = sbase + (rr * ASTR + rc) * 2;
    const uint32_t dAl = dAh + ALO;
    const uint32_t dWh = sbase + WOFF + (rr * ASTR + rc) * 2;
    const uint32_t dWl = dWh + WLO;

    uint32_t ah0, bh0;
    {
        int arow = mq * 32 + (lane & 15);
        int acol = (lane >> 4) << 3;
        ah0 = sbase + (arow * ASTR + acol) * 2;
        int brow = nh * 64 + ((lane >> 4) << 3) + (lane & 7);
        int bcol = ((lane >> 3) & 1) << 3;
        bh0 = sbase + WOFF + (brow * ASTR + bcol) * 2;
    }
    const uint32_t R16 = 16 * ASTR * 2;

    float acc[2][8][4];
#pragma unroll
    for (int f = 0; f < 2; f++)
#pragma unroll
        for (int j = 0; j < 8; j++)
#pragma unroll
            for (int e = 0; e < 4; e++) acc[f][j][e] = 0.0f;

    const int KC = K >> 5;

    {
        cp16(dAh,      gAh);     cp16(dAh + 16, gAh + 8);
        cp16(dAl,      gAl);     cp16(dAl + 16, gAl + 8);
        cp16(dWh,      gWh);     cp16(dWh + 16, gWh + 8);
        cp16(dWl,      gWl);     cp16(dWl + 16, gWl + 8);
        asm volatile("cp.async.commit_group;");
    }

    for (int k = 0; k < KC; k++) {
        asm volatile("cp.async.wait_group 0;");
        __syncthreads();

        int kn = k + 1;
        if (kn < KC) {
            uint32_t off = (uint32_t)(kn & 1) * SB;
            int k0 = kn << 5;
            cp16(dAh + off,      gAh + k0);  cp16(dAh + off + 16, gAh + k0 + 8);
            cp16(dAl + off,      gAl + k0);  cp16(dAl + off + 16, gAl + k0 + 8);
            cp16(dWh + off,      gWh + k0);  cp16(dWh + off + 16, gWh + k0 + 8);
            cp16(dWl + off,      gWl + k0);  cp16(dWl + off + 16, gWl + k0 + 8);
        }
        asm volatile("cp.async.commit_group;");

        uint32_t off = (uint32_t)(k & 1) * SB;
#pragma unroll
        for (int s = 0; s < 2; s++) {
            uint32_t soff = off + s * 32;
            uint32_t a_h[2][4], a_l[2][4], b_h[4][4], b_l[4][4];
            ldsm_x4(ah0 + soff,       a_h[0]);
            ldsm_x4(ah0 + soff + R16, a_h[1]);
            ldsm_x4(ah0 + ALO + soff,       a_l[0]);
            ldsm_x4(ah0 + ALO + soff + R16, a_l[1]);
#pragma unroll
            for (int gq = 0; gq < 4; gq++)
                ldsm_x4(bh0 + soff + gq * R16, b_h[gq]);
#pragma unroll
            for (int f = 0; f < 2; f++)
#pragma unroll
                for (int j = 0; j < 8; j++)
                    mma16816(acc[f][j], a_h[f], b_h[j >> 1][(j & 1) << 1],
                             b_h[j >> 1][((j & 1) << 1) + 1]);
#pragma unroll
            for (int gq = 0; gq < 4; gq++)
                ldsm_x4(bh0 + WLO + soff + gq * R16, b_l[gq]);
#pragma unroll
            for (int f = 0; f < 2; f++)
#pragma unroll
                for (int j = 0; j < 8; j++)
                    mma16816(acc[f][j], a_h[f], b_l[j >> 1][(j & 1) << 1],
                             b_l[j >> 1][((j & 1) << 1) + 1]);
#pragma unroll
            for (int f = 0; f < 2; f++)
#pragma unroll
                for (int j = 0; j < 8; j++)
                    mma16816(acc[f][j], a_l[f], b_h[j >> 1][(j & 1) << 1],
                             b_h[j >> 1][((j & 1) << 1) + 1]);
        }
    }
    __syncthreads();

    const int g = lane >> 2, t = lane & 3;
#pragma unroll
    for (int f = 0; f < 2; f++) {
        int r0 = mq * 32 + f * 16 + g;
        int r1 = r0 + 8;
#pragma unroll
        for (int j = 0; j < 8; j++) {
            int col = nh * 64 + 8 * j + 2 * t;
            float2 bv = *(const float2*)(bias + col);
            float v00 = acc[f][j][0] + bv.x, v01 = acc[f][j][1] + bv.y;
            float v10 = acc[f][j][2] + bv.x, v11 = acc[f][j][3] + bv.y;
            if (SPLIT_OUT) {
                store_split2(Ch + (size_t)r0 * ldc + col, Cl + (size_t)r0 * ldc + col, v00, v01);
                store_split2(Ch + (size_t)r1 * ldc + col, Cl + (size_t)r1 * ldc + col, v10, v11);
            } else {
                *(float2*)(C + (size_t)r0 * ldc + col) = make_float2(v00, v01);
                *(float2*)(C + (size_t)r1 * ldc + col) = make_float2(v10, v11);
            }
        }
    }
}

// Precompute GEMM: grid (N/128, M/128).
__global__ __launch_bounds__(256, 2)
void mma_gemm_nt(const bf16* __restrict__ Ah, const bf16* __restrict__ Al,
                 const bf16* __restrict__ Wh, const bf16* __restrict__ Wl,
                 const float* __restrict__ bias, float* __restrict__ C,
                 int N, int K)
{
    extern __shared__ char dynsm[];
    uint32_t sbase = cvta_smem(dynsm);
    int m0 = blockIdx.y * 128;
    int n0 = blockIdx.x * 128;
    mma_tile128<0>(sbase,
                   Ah + (size_t)m0 * K, Al + (size_t)m0 * K, K,
                   Wh + (size_t)n0 * K, Wl + (size_t)n0 * K, K,
                   bias + n0, C + (size_t)m0 * N + n0, nullptr, nullptr,
                   N, K);
}

// h0 (z=0, split-bf16 output) and c0 (z=1, fp32) in one launch.
__global__ __launch_bounds__(256, 2)
void h0c0_kernel(const float* __restrict__ b0h, const float* __restrict__ b0c)
{
    extern __shared__ char dynsm[];
    uint32_t sbase = cvta_smem(dynsm);
    int n0 = blockIdx.x * 128;
    if (blockIdx.z == 0) {
        mma_tile128<1>(sbase, g_mean_h, g_mean_l, V_,
                       g_W0h_h + (size_t)n0 * V_, g_W0h_l + (size_t)n0 * V_, V_,
                       b0h + n0, nullptr, g_h_h + n0, g_h_l + n0, H_, V_);
    } else {
        mma_tile128<0>(sbase, g_mean_h, g_mean_l, V_,
                       g_W0c_h + (size_t)n0 * V_, g_W0c_l + (size_t)n0 * V_, V_,
                       b0c + n0, g_c + n0, nullptr, nullptr, H_, V_);
    }
}

// ---------------------------------------------------------------------------
// Attention: block pair (b, b+128), each writes half the ctx V-range.
// ---------------------------------------------------------------------------
__device__ __forceinline__
void attn_work(int b, int vhalf, const float* __restrict__ visual,
               const float* __restrict__ Wp, const float* __restrict__ bp,
               const int* __restrict__ ls_rois,
               float* he_s, float* wp_s, float* att)
{
    int tid = threadIdx.x;
    int warp = tid >> 5, lane = tid & 31;

    if (tid < 128) {
        float4 hs = make_float4(0.f, 0.f, 0.f, 0.f);
#pragma unroll
        for (int kp = 0; kp < SK; kp++) {
            float4 hv = ((const float4*)(g_he_p[kp] + b * A_))[tid];
            hs.x += hv.x; hs.y += hv.y; hs.z += hv.z; hs.w += hv.w;
        }
        ((float4*)he_s)[tid] = hs;
        ((float4*)wp_s)[tid] = ((const float4*)Wp)[tid];
    }
    __syncthreads();

    int L = ls_rois[b];

    for (int n = warp; n < NROI; n += 8) {
        float s = 0.0f;
        if (n < L) {
            const float4* vrow = (const float4*)(g_va + ((size_t)b * NROI + n) * A_);
            const float4* he4 = (const float4*)he_s;
            const float4* wp4 = (const float4*)wp_s;
#pragma unroll
            for (int a4 = lane; a4 < A_ / 4; a4 += 32) {
                float4 v = vrow[a4];
                float4 h = he4[a4];
                float4 p = wp4[a4];
                s += p.x * fmaxf(v.x + h.x, 0.0f);
                s += p.y * fmaxf(v.y + h.y, 0.0f);
                s += p.z * fmaxf(v.z + h.z, 0.0f);
                s += p.w * fmaxf(v.w + h.w, 0.0f);
            }
        }
#pragma unroll
        for (int o = 16; o; o >>= 1) s += __shfl_xor_sync(0xffffffffu, s, o);
        if (lane == 0) att[n] = s + bp[0];
    }
    __syncthreads();

    if (tid == 0) {
        float mx = -3.0e38f;
        for (int n = 0; n < L; n++) mx = fmaxf(mx, att[n]);
        float den = 0.0f;
        for (int n = 0; n < L; n++) { float e = expf(att[n] - mx); att[n] = e; den += e; }
        float inv = 1.0f / den;
        for (int n = 0; n < L; n++) att[n] *= inv;
        for (int n = L; n < NROI; n++) att[n] = 0.0f;
    }
    __syncthreads();

    const float4* vb4 = (const float4*)(visual + (size_t)b * NROI * V_);
    int v4 = vhalf * (V_ / 8) + tid;
    float4 s = make_float4(0.f, 0.f, 0.f, 0.f);
#pragma unroll 8
    for (int n = 0; n < NROI; n++) {
        float a = att[n];
        float4 x = vb4[(size_t)n * (V_ / 4) + v4];
        s.x += a * x.x; s.y += a * x.y; s.z += a * x.z; s.w += a * x.w;
    }
    split_store4(g_ctx_h + b * V_ + v4 * 4, g_ctx_l + b * V_ + v4 * 4, s);
    __syncthreads();
}

// ---------------------------------------------------------------------------
// LSTM gates + highway + state update + y. Sums SK ps + SK pa partials.
// ---------------------------------------------------------------------------
__device__ __forceinline__
void gate_work(int b, int t, const float* __restrict__ Wo,
               const float* __restrict__ bo, const int* __restrict__ seq_lens,
               float* __restrict__ y, float* red)
{
    const int HQ = H_ / 4;
    int tid = threadIdx.x;
    bool valid = (t < seq_lens[b]);

    const float4* pi = (const float4*)(g_pi + ((size_t)b * T_ + t) * (6 * H_));
    float4* c4 = (float4*)(g_c + b * H_);

    float g[5][4];
#pragma unroll
    for (int kg = 0; kg < 5; kg++) {
        float4 a = pi[kg * HQ + tid];
        float gx = a.x, gy = a.y, gz = a.z, gw = a.w;
#pragma unroll
        for (int kp = 0; kp < SK; kp++) {
            float4 q = ((const float4*)(g_ps_p[kp] + (size_t)b * (5 * H_)))[kg * HQ + tid];
            float4 r = ((const float4*)(g_pa_p[kp] + (size_t)b * (5 * H_)))[kg * HQ + tid];
            gx += q.x + r.x; gy += q.y + r.y; gz += q.z + r.z; gw += q.w + r.w;
        }
        g[kg][0] = gx; g[kg][1] = gy; g[kg][2] = gz; g[kg][3] = gw;
    }
    float4 s5 = pi[5 * HQ + tid];
    float pi5[4] = {s5.x, s5.y, s5.z, s5.w};
    float4 cv = c4[tid];
    float cc[4] = {cv.x, cv.y, cv.z, cv.w};
    float4 wo = ((const float4*)Wo)[tid];
    float wof[4] = {wo.x, wo.y, wo.z, wo.w};

    float out[4], mem[4], part = 0.0f;
#pragma unroll
    for (int e = 0; e < 4; e++) {
        float ig = sigmoidf(g[0][e]);
        float fg = sigmoidf(g[1][e]);
        float mi = tanhf(g[2][e]);
        float og = sigmoidf(g[3][e]);
        float m  = ig * mi + fg * cc[e];
        float o  = og * tanhf(m);
        float hw = sigmoidf(g[4][e]);
        out[e] = hw * o + (1.0f - hw) * pi5[e];
        mem[e] = m;
        part += out[e] * wof[e];
    }

    if (valid) {
        split_store4(g_h_h + b * H_ + 4 * tid, g_h_l + b * H_ + 4 * tid,
                     make_float4(out[0], out[1], out[2], out[3]));
        c4[tid] = make_float4(mem[0], mem[1], mem[2], mem[3]);
    }

#pragma unroll
    for (int o = 16; o; o >>= 1) part += __shfl_xor_sync(0xffffffffu, part, o);
    if ((tid & 31) == 0) red[tid >> 5] = part;
    __syncthreads();
    if (tid == 0) {
        float s = 0.0f;
#pragma unroll
        for (int w = 0; w < 8; w++) s += red[w];
        y[b * T_ + t] = valid ? (s + bo[0]) : 0.0f;
    }
    __syncthreads();
}

// ---------------------------------------------------------------------------
// Persistent recurrent-loop kernel: 128x64 tensor tiles, split-K x4 (R13 cfg).
// ---------------------------------------------------------------------------
__global__ __launch_bounds__(256, 2)
void loop_kernel(const float* __restrict__ bs, const float* __restrict__ bh,
                 const float* __restrict__ ba,
                 const float* __restrict__ Wp, const float* __restrict__ bp,
                 const float* __restrict__ Wo, const float* __restrict__ bo,
                 const float* __restrict__ visual,
                 const int* __restrict__ ls_rois,
                 const int* __restrict__ seq_lens,
                 float* __restrict__ y)
{
    extern __shared__ char dynsm[];
    uint32_t sbase = cvta_smem(dynsm);

    __shared__ float he_s[A_];
    __shared__ float wp_s[A_];
    __shared__ float att[NROI];
    __shared__ float red[8];

    const int NT1 = ((5 * H_ + A_) / 64) * SK;   // 352 tiles, K=256
    const int NT2 = ((5 * H_) / 64) * SK;        // 320 tiles, K=512
    const int KH1 = H_ / SK;                      // 256
    const int KH2 = V_ / SK;                      // 512

    for (int t = 0; t < T_; t++) {
        // ---- phase 1: [ps | he] = h @ [Ws ; Wh]^T ----
        for (int tile = blockIdx.x; tile < NT1; tile += NB) {
            int kp = tile & (SK - 1), nt = tile >> 2;
            int n0 = nt << 6;
            const bf16* Ahp = g_h_h + kp * KH1;
            const bf16* Alp = g_h_l + kp * KH1;
            if (n0 < 5 * H_) {
                mma_tile64(sbase, Ahp, Alp, H_,
                         g_Ws_h + (size_t)n0 * H_ + kp * KH1,
                         g_Ws_l + (size_t)n0 * H_ + kp * KH1, H_,
                         kp ? g_zero : (bs + n0),
                         g_ps_p[kp] + n0, 5 * H_, KH1);
            } else {
                int m = n0 - 5 * H_;
                mma_tile64(sbase, Ahp, Alp, H_,
                         g_Wh_h + (size_t)m * H_ + kp * KH1,
                         g_Wh_l + (size_t)m * H_ + kp * KH1, H_,
                         kp ? g_zero : (bh + m),
                         g_he_p[kp] + m, A_, KH1);
            }
        }
        grid_sync();

        // ---- phase 2: attention -> ctx (2 blocks per batch element) ----
        if (blockIdx.x < 2 * B_)
            attn_work(blockIdx.x & (B_ - 1), blockIdx.x >> 7,
                      visual, Wp, bp, ls_rois, he_s, wp_s, att);
        grid_sync();

        // ---- phase 3: pa = ctx @ Wa^T ----
        for (int tile = blockIdx.x; tile < NT2; tile += NB) {
            int kp = tile & (SK - 1), nt = tile >> 2;
            int n0 = nt << 6;
            mma_tile64(sbase,
                     g_ctx_h + kp * KH2, g_ctx_l + kp * KH2, V_,
                     g_Wa_h + (size_t)n0 * V_ + kp * KH2,
                     g_Wa_l + (size_t)n0 * V_ + kp * KH2, V_,
                     kp ? g_zero : (ba + n0),
                     g_pa_p[kp] + n0, 5 * H_, KH2);
        }
        grid_sync();

        // ---- phase 4: gates + state update + y ----
        if (blockIdx.x < B_)
            gate_work(blockIdx.x, t, Wo, bo, seq_lens, y, red);
        grid_sync();
    }
}

// ---------------------------------------------------------------------------
extern "C" void kernel_launch(void* const* d_in, const int* in_sizes, int n_in,
                              void* d_out, int out_size)
{
    const float* x      = (const float*)d_in[0];
    const float* visual = (const float*)d_in[1];
    const float* Wi     = (const float*)d_in[2];
    const float* bi     = (const float*)d_in[3];
    const float* Ws     = (const float*)d_in[4];
    const float* bs     = (const float*)d_in[5];
    const float* Wa     = (const float*)d_in[6];
    const float* ba     = (const float*)d_in[7];
    const float* Wv     = (const float*)d_in[8];
    const float* bv     = (const float*)d_in[9];
    const float* Wh     = (const float*)d_in[10];
    const float* bh     = (const float*)d_in[11];
    const float* Wp     = (const float*)d_in[12];
    const float* bp     = (const float*)d_in[13];
    const float* W0h    = (const float*)d_in[14];
    const float* b0h    = (const float*)d_in[15];
    const float* W0c    = (const float*)d_in[16];
    const float* b0c    = (const float*)d_in[17];
    const float* Wo     = (const float*)d_in[18];
    const float* bo     = (const float*)d_in[19];
    const int* ls_rois  = (const int*)d_in[20];
    const int* seq_lens = (const int*)d_in[21];
    float* y = (float*)d_out;

    cudaFuncSetAttribute(loop_kernel,
                         cudaFuncAttributeMaxDynamicSharedMemorySize, SMEM_LOOP);
    cudaFuncSetAttribute(mma_gemm_nt,
                         cudaFuncAttributeMaxDynamicSharedMemorySize, SMEM_PRE);
    cudaFuncSetAttribute(h0c0_kernel,
                         cudaFuncAttributeMaxDynamicSharedMemorySize, SMEM_PRE);

    float *p_va, *p_pi;
    cudaGetSymbolAddress((void**)&p_va, g_va);
    cudaGetSymbolAddress((void**)&p_pi, g_pi);
    bf16 *px_h, *px_l, *pv_h, *pv_l;
    bf16 *pWi_h, *pWi_l, *pWs_h, *pWs_l, *pWa_h, *pWa_l, *pWv_h, *pWv_l;
    bf16 *pWh_h, *pWh_l, *pW0h_h, *pW0h_l, *pW0c_h, *pW0c_l;
    cudaGetSymbolAddress((void**)&px_h, g_x_h);   cudaGetSymbolAddress((void**)&px_l, g_x_l);
    cudaGetSymbolAddress((void**)&pv_h, g_vis_h); cudaGetSymbolAddress((void**)&pv_l, g_vis_l);
    cudaGetSymbolAddress((void**)&pWi_h, g_Wi_h); cudaGetSymbolAddress((void**)&pWi_l, g_Wi_l);
    cudaGetSymbolAddress((void**)&pWs_h, g_Ws_h); cudaGetSymbolAddress((void**)&pWs_l, g_Ws_l);
    cudaGetSymbolAddress((void**)&pWa_h, g_Wa_h); cudaGetSymbolAddress((void**)&pWa_l, g_Wa_l);
    cudaGetSymbolAddress((void**)&pWv_h, g_Wv_h); cudaGetSymbolAddress((void**)&pWv_l, g_Wv_l);
    cudaGetSymbolAddress((void**)&pWh_h, g_Wh_h); cudaGetSymbolAddress((void**)&pWh_l, g_Wh_l);
    cudaGetSymbolAddress((void**)&pW0h_h, g_W0h_h); cudaGetSymbolAddress((void**)&pW0h_l, g_W0h_l);
    cudaGetSymbolAddress((void**)&pW0c_h, g_W0c_h); cudaGetSymbolAddress((void**)&pW0c_l, g_W0c_l);

    // ---- launch 1: all loop-invariant splits fused ----
    SJobs jobs;
    jobs.j[0] = { x,      px_h,  px_l,  (B_ * T_ * DIN) / 4 };
    jobs.j[1] = { visual, pv_h,  pv_l,  (B_ * NROI * V_) / 4 };
    jobs.j[2] = { Wi,     pWi_h, pWi_l, (6 * H_ * DIN) / 4 };
    jobs.j[3] = { Ws,     pWs_h, pWs_l, (5 * H_ * H_) / 4 };
    jobs.j[4] = { Wa,     pWa_h, pWa_l, (5 * H_ * V_) / 4 };
    jobs.j[5] = { Wv,     pWv_h, pWv_l, (A_ * V_) / 4 };
    jobs.j[6] = { Wh,     pWh_h, pWh_l, (A_ * H_) / 4 };
    jobs.j[7] = { W0h,    pW0h_h, pW0h_l, (H_ * V_) / 4 };
    jobs.j[8] = { W0c,    pW0c_h, pW0c_l, (H_ * V_) / 4 };
    split_all_kernel<<<dim3(148, 9), 256>>>(jobs);

    // ---- launch 2: mean (writes splits directly) ----
    mean_vis_kernel<<<B_, 256>>>(visual, ls_rois);

    // ---- launch 3: pi = x @ Wi^T + bi ----
    mma_gemm_nt<<<dim3(6 * H_ / 128, B_ * T_ / 128), 256, SMEM_PRE>>>(
        px_h, px_l, pWi_h, pWi_l, bi, p_pi, 6 * H_, DIN);

    // ---- launch 4: va = visual @ Wv^T + bv ----
    mma_gemm_nt<<<dim3(A_ / 128, B_ * NROI / 128), 256, SMEM_PRE>>>(
        pv_h, pv_l, pWv_h, pWv_l, bv, p_va, A_, V_);

    // ---- launch 5: h0 (split output) + c0 (fp32) ----
    h0c0_kernel<<<dim3(H_ / 128, 1, 2), 256, SMEM_PRE>>>(b0h, b0c);

    // ---- launch 6: entire recurrent loop ----
    loop_kernel<<<NB, 256, SMEM_LOOP>>>(bs, bh, ba, Wp, bp, Wo, bo,
                                        visual, ls_rois, seq_lens, y);
}